// round 11
// baseline (speedup 1.0000x reference)
#include <cuda_runtime.h>

// ---- problem constants -----------------------------------------------------
#define BGRAPH 64
#define N_PER  2048
#define FDIM   64
#define NE     1048576
#define NEH    (NE / 2)
#define NNODE  (BGRAPH * N_PER)      // 131072
#define KSEL   1639                   // ceil(0.8*2048)
#define PSEL   (BGRAPH * KSEL)        // 104896
#define K0     209715                 // ascending rank: E-1 - int(0.8*(E-1))

// ---- output layout (float32, concatenated in return order) -----------------
#define OFF_X      0
#define OFF_EIDX   6713344            // PSEL*FDIM
#define OFF_EATTR  8810496            // + 2*NE
#define OFF_BATCH  17199104           // + 8*NE
#define OFF_SEL    17304000           // + PSEL

// ---- device scratch ---------------------------------------------------------
__device__ float        g_S[NE];
__device__ int          g_new_idx[NNODE];
__device__ int          g_perm[PSEL];
__device__ unsigned int g_hist1[65536];
__device__ unsigned int g_hist2[65536];
__device__ unsigned int g_sel_hi;
__device__ unsigned int g_rem;
__device__ float        g_th;

// ---- per-graph top-k via bitonic sort; also zeroes both histograms ----------
__global__ void topk_kernel(const float* __restrict__ score) {
    __shared__ unsigned long long keys[N_PER];
    const int b = blockIdx.x;
    const int t = threadIdx.x;           // 1024 threads

    {   int h = b * 1024 + t; g_hist1[h] = 0u; g_hist2[h] = 0u; }

    for (int i = t; i < N_PER; i += 1024) {
        float s = score[b * N_PER + i];
        unsigned int bits = __float_as_uint(s);
        bits = (bits & 0x80000000u) ? ~bits : (bits | 0x80000000u);
        unsigned int dk = ~bits;
        keys[i] = (((unsigned long long)dk) << 32) | (unsigned int)i;
        g_new_idx[b * N_PER + i] = -1;
    }
    __syncthreads();

    for (int k = 2; k <= N_PER; k <<= 1) {
        for (int j = k >> 1; j > 0; j >>= 1) {
            for (int i = t; i < N_PER; i += 1024) {
                int ixj = i ^ j;
                if (ixj > i) {
                    unsigned long long a = keys[i], c = keys[ixj];
                    bool up = ((i & k) == 0);
                    if ((a > c) == up) { keys[i] = c; keys[ixj] = a; }
                }
            }
            __syncthreads();
        }
    }

    for (int i = t; i < KSEL; i += 1024) {
        int idx  = (int)(keys[i] & 0xffffffffu);
        int node = b * N_PER + idx;
        int newp = b * KSEL + i;
        g_new_idx[node] = newp;
        g_perm[newp]    = node;
    }
}

// ---- x_out gather -----------------------------------------------------------
__global__ void gather_x_kernel(const float* __restrict__ x, float* __restrict__ out) {
    int tid = blockIdx.x * blockDim.x + threadIdx.x;   // PSEL*16 threads
    if (tid >= PSEL * 16) return;
    int row = tid >> 4, c = tid & 15;
    int node = g_perm[row];
    float4 v = ((const float4*)x)[(size_t)node * 16 + c];
    ((float4*)(out + OFF_X))[(size_t)row * 16 + c] = v;
}

// ---- batch_out: pure function of index --------------------------------------
__global__ void batch_kernel(float* __restrict__ out) {
    int p = blockIdx.x * blockDim.x + threadIdx.x;
    if (p >= PSEL) return;
    out[OFF_BATCH + p] = (float)((unsigned)p / (unsigned)KSEL);
}

// ---- S computation only: 2 edges per thread, 8 lanes per edge ---------------
// No streaming stores -> x stays L2-resident; 8 independent LDG.128 in flight.
// Per-edge arithmetic identical to the previously passing kernel.
__global__ void edge_s_kernel(const int* __restrict__ ei,
                              const float* __restrict__ x) {
    int g = blockIdx.x * blockDim.x + threadIdx.x;     // NEH*8 threads
    int grp = g >> 3, lane8 = g & 7;
    if (grp >= NEH) return;
    int e0 = grp, e1 = grp + NEH;

    int r0 = ei[e0], c0 = ei[NE + e0];
    int r1 = ei[e1], c1 = ei[NE + e1];

    const float4* pr0 = (const float4*)(x + (size_t)r0 * FDIM);
    const float4* pc0 = (const float4*)(x + (size_t)c0 * FDIM);
    const float4* pr1 = (const float4*)(x + (size_t)r1 * FDIM);
    const float4* pc1 = (const float4*)(x + (size_t)c1 * FDIM);

    // batch all 8 row loads (independent) before any arithmetic
    float4 A0 = pr0[lane8], A1 = pr0[lane8 + 8];
    float4 B0 = pc0[lane8], B1 = pc0[lane8 + 8];
    float4 C0 = pr1[lane8], C1 = pr1[lane8 + 8];
    float4 D0 = pc1[lane8], D1 = pc1[lane8 + 8];

    float dx, dy, dz, dw;
    float acc0 = 0.0f, acc1 = 0.0f;
    dx = A0.x-B0.x; dy = A0.y-B0.y; dz = A0.z-B0.z; dw = A0.w-B0.w;
    acc0 += dx*dx + dy*dy + dz*dz + dw*dw;
    dx = A1.x-B1.x; dy = A1.y-B1.y; dz = A1.z-B1.z; dw = A1.w-B1.w;
    acc0 += dx*dx + dy*dy + dz*dz + dw*dw;
    dx = C0.x-D0.x; dy = C0.y-D0.y; dz = C0.z-D0.z; dw = C0.w-D0.w;
    acc1 += dx*dx + dy*dy + dz*dz + dw*dw;
    dx = C1.x-D1.x; dy = C1.y-D1.y; dz = C1.z-D1.z; dw = C1.w-D1.w;
    acc1 += dx*dx + dy*dy + dz*dz + dw*dw;

#pragma unroll
    for (int o = 4; o > 0; o >>= 1) {
        acc0 += __shfl_down_sync(0xffffffffu, acc0, o, 8);
        acc1 += __shfl_down_sync(0xffffffffu, acc1, o, 8);
    }

    if (lane8 == 0) {
        float S0 = expf(acc0 > 0.0f ? sqrtf(acc0) : 0.0f);   // _safe_norm
        float S1 = expf(acc1 > 0.0f ? sqrtf(acc1) : 0.0f);
        g_S[e0] = S0;
        g_S[e1] = S1;
        atomicAdd(&g_hist1[__float_as_uint(S0) >> 16], 1u);
        atomicAdd(&g_hist1[__float_as_uint(S1) >> 16], 1u);
    }
}

// ---- streaming remap + attr copy: 2 lanes per edge --------------------------
__global__ void edge_copy_kernel(const int* __restrict__ ei,
                                 const float* __restrict__ eattr,
                                 float* __restrict__ out) {
    int g = blockIdx.x * blockDim.x + threadIdx.x;     // NE*2 threads
    int e = g >> 1, lane2 = g & 1;
    if (e >= NE) return;

    int node = ei[(size_t)lane2 * NE + e];             // lane0: row, lane1: col
    int ni = g_new_idx[node];
    int other = __shfl_xor_sync(0xffffffffu, ni, 1);
    bool valid = (ni >= 0) && (other >= 0);

    if (lane2 == 0) {
        out[OFF_EIDX + e]      = (float)(valid ? ni    : -1);
        out[OFF_EIDX + NE + e] = (float)(valid ? other : -1);
    }
    float4 a = valid ? ((const float4*)eattr)[(size_t)e * 2 + lane2]
                     : make_float4(0.f, 0.f, 0.f, 0.f);
    ((float4*)(out + OFF_EATTR))[(size_t)e * 2 + lane2] = a;
}

// ---- hierarchical k-th locate in 65536-bin histogram ------------------------
__device__ __forceinline__ void find_kth_65536(const unsigned* __restrict__ hist,
                                               unsigned k, int mode) {
    __shared__ unsigned csum[64];
    __shared__ unsigned cpre[64];
    __shared__ int      sel_chunk;
    __shared__ unsigned rem_s;
    __shared__ unsigned warpsum[32];

    const int t = threadIdx.x;
    const int lane = t & 31, w = t >> 5;

    const uint4* h4 = (const uint4*)hist;
    #pragma unroll
    for (int cc = 0; cc < 2; cc++) {
        int c = w * 2 + cc;
        unsigned s = 0;
        #pragma unroll
        for (int i = lane; i < 256; i += 32) {
            uint4 v = h4[c * 256 + i];
            s += v.x + v.y + v.z + v.w;
        }
        #pragma unroll
        for (int o = 16; o > 0; o >>= 1) s += __shfl_down_sync(~0u, s, o);
        if (lane == 0) csum[c] = s;
    }
    __syncthreads();

    if (t < 64) {
        unsigned s = 0;
        for (int i = 0; i < t; i++) s += csum[i];
        cpre[t] = s;
    }
    __syncthreads();
    if (t < 64) {
        if (k >= cpre[t] && k < cpre[t] + csum[t]) { sel_chunk = t; rem_s = k - cpre[t]; }
    }
    __syncthreads();

    const int C = sel_chunk;
    const unsigned kk = rem_s;
    unsigned h = hist[C * 1024 + t];

    unsigned incl = h;
    #pragma unroll
    for (int o = 1; o < 32; o <<= 1) {
        unsigned n = __shfl_up_sync(~0u, incl, o);
        if (lane >= o) incl += n;
    }
    if (lane == 31) warpsum[w] = incl;
    __syncthreads();
    if (w == 0) {
        unsigned ws = warpsum[lane];
        #pragma unroll
        for (int o = 1; o < 32; o <<= 1) {
            unsigned n = __shfl_up_sync(~0u, ws, o);
            if (lane >= o) ws += n;
        }
        warpsum[lane] = ws;
    }
    __syncthreads();
    unsigned pre = ((w == 0) ? 0u : warpsum[w - 1]) + incl - h;

    if (kk >= pre && kk < pre + h) {
        unsigned bin = (unsigned)(C * 1024 + t);
        if (mode == 0) { g_sel_hi = bin; g_rem = kk - pre; }
        else           { g_th = __uint_as_float((g_sel_hi << 16) | bin); }
    }
}

__global__ void scan1_kernel() { find_kth_65536(g_hist1, K0, 0); }

__global__ void hist2_kernel() {
    int e = blockIdx.x * blockDim.x + threadIdx.x;
    if (e >= NE) return;
    unsigned b = __float_as_uint(g_S[e]);
    if ((b >> 16) == g_sel_hi) atomicAdd(&g_hist2[b & 0xffffu], 1u);
}

__global__ void scan2_kernel() { find_kth_65536(g_hist2, g_rem, 1); }

__global__ void select_kernel(float* __restrict__ out) {
    int e = blockIdx.x * blockDim.x + threadIdx.x;
    if (e >= NE) return;
    out[OFF_SEL + e] = (g_S[e] > g_th) ? 1.0f : 0.0f;
}

extern "C" void kernel_launch(void* const* d_in, const int* in_sizes, int n_in,
                              void* d_out, int out_size) {
    const float* x     = (const float*)d_in[0];
    const float* score = (const float*)d_in[1];
    const int*   ei    = (const int*)d_in[2];
    const float* eattr = (const float*)d_in[3];
    float* out = (float*)d_out;

    topk_kernel<<<BGRAPH, 1024>>>(score);                       // idx 0
    gather_x_kernel<<<(PSEL * 16 + 255) / 256, 256>>>(x, out);  // idx 1
    batch_kernel<<<(PSEL + 255) / 256, 256>>>(out);             // idx 2
    edge_s_kernel<<<(NEH * 8) / 256, 256>>>(ei, x);             // idx 3 (profiled)
    edge_copy_kernel<<<(NE * 2) / 256, 256>>>(ei, eattr, out);  // idx 4
    scan1_kernel<<<1, 1024>>>();                                // idx 5
    hist2_kernel<<<NE / 256, 256>>>();                          // idx 6
    scan2_kernel<<<1, 1024>>>();                                // idx 7
    select_kernel<<<NE / 256, 256>>>(out);                      // idx 8
}